// round 2
// baseline (speedup 1.0000x reference)
#include <cuda_runtime.h>

// Problem constants
constexpr int BB   = 128;   // batch
constexpr int CC   = 64;    // state channels
constexpr int K1   = 192;   // 3*C perception channels
constexpr int M1   = 512;   // MLP dim
constexpr int HH   = 40;
constexpr int WW   = 40;
constexpr int HWp  = 1600;  // H*W
constexpr float LN_EPS = 1e-5f;

// Scratch (static device arrays; allocation-free per harness rules)
__device__ float g_perc[(size_t)BB * K1 * HWp];        // 157 MB
__device__ float g_y[(size_t)BB * M1 * HWp];           // 419 MB
__device__ float g_part[BB * 100 * 2];                 // per-block partial sums
__device__ float g_stats[BB * 2];                      // mu, rstd per sample

// ---------------------------------------------------------------------------
// Kernel 1: depthwise sobel_x / sobel_y / identity perception
// out channel layout: [b][3c+{0:sx,1:sy,2:id}][p]
// ---------------------------------------------------------------------------
__global__ void perc_kernel(const float* __restrict__ state) {
    int idx = blockIdx.x * blockDim.x + threadIdx.x;
    if (idx >= BB * CC * HWp) return;
    int p  = idx % HWp;
    int bc = idx / HWp;
    int c  = bc % CC;
    int b  = bc / CC;
    int h = p / WW, w = p % WW;
    const float* s = state + (size_t)(b * CC + c) * HWp;
    float v[3][3];
#pragma unroll
    for (int dy = -1; dy <= 1; dy++)
#pragma unroll
        for (int dx = -1; dx <= 1; dx++) {
            int hh = h + dy, ww2 = w + dx;
            v[dy + 1][dx + 1] =
                (hh >= 0 && hh < HH && ww2 >= 0 && ww2 < WW) ? s[hh * WW + ww2] : 0.f;
        }
    float sx = -v[0][0] + v[0][2] - 2.f * v[1][0] + 2.f * v[1][2] - v[2][0] + v[2][2];
    float sy = -v[0][0] - 2.f * v[0][1] - v[0][2] + v[2][0] + 2.f * v[2][1] + v[2][2];
    float id = v[1][1];
    float* o = g_perc + (size_t)(b * K1 + 3 * c) * HWp + p;
    o[0]        = sx;
    o[HWp]      = sy;
    o[2 * HWp]  = id;
}

// ---------------------------------------------------------------------------
// Kernel 2: GEMM1  Y[b] = W1[512,192] @ P[b][192,1600], plus per-tile stats
// Grid: (nt=25, mt=4, b=128). Block 256. BM=128, BN=64, BK=16.
// ---------------------------------------------------------------------------
constexpr int BM1 = 128, BN1 = 64, BK1 = 16;

__global__ __launch_bounds__(256) void gemm1_kernel(const float* __restrict__ w1) {
    int b  = blockIdx.z;
    int mt = blockIdx.y;
    int nt = blockIdx.x;
    __shared__ float As[BK1][BM1];
    __shared__ float Bs[BK1][BN1];
    int tid = threadIdx.x;
    int tx = tid % 16;  // n: 16 * 4 = 64
    int ty = tid / 16;  // m: 16 * 8 = 128
    float acc[8][4] = {};

    const float* Ag = w1 + (size_t)mt * BM1 * K1;
    const float* Bg = g_perc + (size_t)b * K1 * HWp + nt * BN1;

    for (int k0 = 0; k0 < K1; k0 += BK1) {
        // A tile 128x16 (2 float4 per thread), transposed into As[k][m]
#pragma unroll
        for (int i = 0; i < 2; i++) {
            int f4i = tid + i * 256;           // 0..511
            int r   = f4i >> 2;                // 0..127
            int cc  = (f4i & 3) * 4;           // 0,4,8,12
            float4 a = *reinterpret_cast<const float4*>(Ag + r * K1 + k0 + cc);
            As[cc + 0][r] = a.x;
            As[cc + 1][r] = a.y;
            As[cc + 2][r] = a.z;
            As[cc + 3][r] = a.w;
        }
        // B tile 16x64 (1 float4 per thread)
        {
            int r  = tid >> 4;           // 0..15
            int cc = (tid & 15) * 4;     // 0..60
            float4 bv = *reinterpret_cast<const float4*>(Bg + (size_t)(k0 + r) * HWp + cc);
            *reinterpret_cast<float4*>(&Bs[r][cc]) = bv;
        }
        __syncthreads();
#pragma unroll
        for (int k = 0; k < BK1; k++) {
            float ra[8], rb[4];
#pragma unroll
            for (int i = 0; i < 8; i++) ra[i] = As[k][ty * 8 + i];
#pragma unroll
            for (int j = 0; j < 4; j++) rb[j] = Bs[k][tx * 4 + j];
#pragma unroll
            for (int i = 0; i < 8; i++)
#pragma unroll
                for (int j = 0; j < 4; j++) acc[i][j] += ra[i] * rb[j];
        }
        __syncthreads();
    }

    // store Y + accumulate per-thread stats
    float s = 0.f, s2 = 0.f;
    float* Cg = g_y + (size_t)b * M1 * HWp + (size_t)(mt * BM1) * HWp + nt * BN1;
#pragma unroll
    for (int i = 0; i < 8; i++) {
        int m = ty * 8 + i;
        float4 v4 = make_float4(acc[i][0], acc[i][1], acc[i][2], acc[i][3]);
        *reinterpret_cast<float4*>(Cg + (size_t)m * HWp + tx * 4) = v4;
        s  += v4.x + v4.y + v4.z + v4.w;
        s2 += v4.x * v4.x + v4.y * v4.y + v4.z * v4.z + v4.w * v4.w;
    }

    // deterministic block reduction -> partials
    __shared__ float red[256];
    red[tid] = s;
    __syncthreads();
    for (int o = 128; o > 0; o >>= 1) {
        if (tid < o) red[tid] += red[tid + o];
        __syncthreads();
    }
    float bs = red[0];
    __syncthreads();
    red[tid] = s2;
    __syncthreads();
    for (int o = 128; o > 0; o >>= 1) {
        if (tid < o) red[tid] += red[tid + o];
        __syncthreads();
    }
    if (tid == 0) {
        int pi = (b * 4 + mt) * 25 + nt;   // == b*100 + mt*25 + nt
        g_part[pi * 2 + 0] = bs;
        g_part[pi * 2 + 1] = red[0];
    }
}

// ---------------------------------------------------------------------------
// Kernel 3: finalize per-sample mean / rstd (deterministic fixed-order sum)
// ---------------------------------------------------------------------------
__global__ void stats_kernel() {
    int b = threadIdx.x;
    if (b >= BB) return;
    float s = 0.f, s2 = 0.f;
    for (int i = 0; i < 100; i++) {
        s  += g_part[(b * 100 + i) * 2 + 0];
        s2 += g_part[(b * 100 + i) * 2 + 1];
    }
    float inv = 1.f / (float)(M1 * HWp);
    float mu  = s * inv;
    float var = s2 * inv - mu * mu;
    g_stats[b * 2 + 0] = mu;
    g_stats[b * 2 + 1] = rsqrtf(var + LN_EPS);
}

// ---------------------------------------------------------------------------
// Kernel 4: GEMM2  Z = W2[64,512] @ relu(LN(Y)) + epilogue (mask, alive, residual)
// Grid: (nt=25, 1, b=128). Block 256. BM=64, BN=64, BK=32.
// ---------------------------------------------------------------------------
constexpr int BM2 = 64, BN2 = 64, BK2 = 32;

__global__ __launch_bounds__(256) void gemm2_kernel(
    const float* __restrict__ w2, const float* __restrict__ lnw,
    const float* __restrict__ lnb, const float* __restrict__ state,
    const int* __restrict__ mask, float* __restrict__ out) {
    int b  = blockIdx.z;
    int nt = blockIdx.x;
    __shared__ float As[BK2][BM2];
    __shared__ float Bs[BK2][BN2];
    __shared__ float scl[BN2];
    int tid = threadIdx.x;
    int tx = tid % 16;  // n: 16*4 = 64
    int ty = tid / 16;  // m: 16*4 = 64

    float mu   = g_stats[b * 2 + 0];
    float rstd = g_stats[b * 2 + 1];

    // per-column update scale: mask[p] * (maxpool3x3(state[:,3]) > 0.1)
    if (tid < BN2) {
        int p = nt * BN2 + tid;
        int h = p / WW, w = p % WW;
        const float* alive = state + ((size_t)b * CC + 3) * HWp;
        float mx = -1e30f;
#pragma unroll
        for (int dy = -1; dy <= 1; dy++)
#pragma unroll
            for (int dx = -1; dx <= 1; dx++) {
                int hh = h + dy, ww2 = w + dx;
                if (hh >= 0 && hh < HH && ww2 >= 0 && ww2 < WW)
                    mx = fmaxf(mx, alive[hh * WW + ww2]);
            }
        scl[tid] = (mx > 0.1f ? 1.f : 0.f) * (float)mask[p];
    }

    float acc[4][4] = {};
    const float* Yb = g_y + (size_t)b * M1 * HWp + nt * BN2;
    const float* Lw = lnw + nt * BN2;
    const float* Lb = lnb + nt * BN2;

    for (int k0 = 0; k0 < M1; k0 += BK2) {
        // A: w2 tile 64x32, transposed into As[k][m]
#pragma unroll
        for (int i = 0; i < 2; i++) {
            int f4i = tid + i * 256;        // 0..511
            int r   = f4i >> 3;             // 0..63
            int cc  = (f4i & 7) * 4;        // 0..28
            float4 a = *reinterpret_cast<const float4*>(w2 + r * M1 + k0 + cc);
            As[cc + 0][r] = a.x;
            As[cc + 1][r] = a.y;
            As[cc + 2][r] = a.z;
            As[cc + 3][r] = a.w;
        }
        // B: relu(LN(Y)) tile 32x64
#pragma unroll
        for (int i = 0; i < 2; i++) {
            int f4i = tid + i * 256;
            int r   = f4i >> 4;             // 0..31
            int cc  = (f4i & 15) * 4;
            size_t off = (size_t)(k0 + r) * HWp + cc;
            float4 yv = *reinterpret_cast<const float4*>(Yb + off);
            float4 wv = *reinterpret_cast<const float4*>(Lw + off);
            float4 bv = *reinterpret_cast<const float4*>(Lb + off);
            float4 r4;
            r4.x = fmaxf((yv.x - mu) * rstd * wv.x + bv.x, 0.f);
            r4.y = fmaxf((yv.y - mu) * rstd * wv.y + bv.y, 0.f);
            r4.z = fmaxf((yv.z - mu) * rstd * wv.z + bv.z, 0.f);
            r4.w = fmaxf((yv.w - mu) * rstd * wv.w + bv.w, 0.f);
            *reinterpret_cast<float4*>(&Bs[r][cc]) = r4;
        }
        __syncthreads();
#pragma unroll
        for (int k = 0; k < BK2; k++) {
            float ra[4], rb[4];
#pragma unroll
            for (int i = 0; i < 4; i++) ra[i] = As[k][ty * 4 + i];
#pragma unroll
            for (int j = 0; j < 4; j++) rb[j] = Bs[k][tx * 4 + j];
#pragma unroll
            for (int i = 0; i < 4; i++)
#pragma unroll
                for (int j = 0; j < 4; j++) acc[i][j] += ra[i] * rb[j];
        }
        __syncthreads();
    }

    // epilogue: out = state + z * scale
    const float* Sb = state + (size_t)b * CC * HWp + nt * BN2;
    float* Ob = out + (size_t)b * CC * HWp + nt * BN2;
#pragma unroll
    for (int i = 0; i < 4; i++) {
        int m = ty * 4 + i;
        size_t off = (size_t)m * HWp + tx * 4;
        float4 sv = *reinterpret_cast<const float4*>(Sb + off);
        float4 ov;
        ov.x = sv.x + acc[i][0] * scl[tx * 4 + 0];
        ov.y = sv.y + acc[i][1] * scl[tx * 4 + 1];
        ov.z = sv.z + acc[i][2] * scl[tx * 4 + 2];
        ov.w = sv.w + acc[i][3] * scl[tx * 4 + 3];
        *reinterpret_cast<float4*>(Ob + off) = ov;
    }
}

// ---------------------------------------------------------------------------
extern "C" void kernel_launch(void* const* d_in, const int* in_sizes, int n_in,
                              void* d_out, int out_size) {
    const float* state = (const float*)d_in[0];
    const float* w1    = (const float*)d_in[1];
    const float* lnw   = (const float*)d_in[2];
    const float* lnb   = (const float*)d_in[3];
    const float* w2    = (const float*)d_in[4];
    const int*   mask  = (const int*)d_in[5];
    float* out = (float*)d_out;

    perc_kernel<<<(BB * CC * HWp) / 256, 256>>>(state);
    gemm1_kernel<<<dim3(25, 4, BB), 256>>>(w1);
    stats_kernel<<<1, 128>>>();
    gemm2_kernel<<<dim3(25, 1, BB), 256>>>(w2, lnw, lnb, state, mask, out);
}

// round 4
// speedup vs baseline: 1.0390x; 1.0390x over previous
#include <cuda_runtime.h>
#include <cuda_bf16.h>
#include <cstdint>

// ---------------------------------------------------------------------------
// Problem constants
// ---------------------------------------------------------------------------
constexpr int BB   = 128;
constexpr int CC   = 64;
constexpr int K1   = 192;    // 3*C perception channels
constexpr int M1   = 512;    // MLP dim
constexpr int HH   = 40;
constexpr int WW   = 40;
constexpr int PX   = 1600;   // H*W
constexpr int PXP  = 1664;   // padded to 13*128
constexpr float LN_EPS = 1e-5f;

constexpr int KP   = 384;    // perc row: [hi(192) | lo(192)] bf16
constexpr int W2K  = 1024;   // w2split row: [hi(512) | lo(512)] bf16

// ---------------------------------------------------------------------------
// Device scratch
// ---------------------------------------------------------------------------
__device__ __nv_bfloat16 g_perc[(size_t)BB * PXP * KP];   // 163 MB
__device__ float         g_y[(size_t)BB * PXP * M1];      // 436 MB
__device__ __nv_bfloat16 g_w1s[M1 * KP];                  // [512][384]
__device__ __nv_bfloat16 g_w2s[CC * W2K];                 // [64][1024]
__device__ float         g_lnwT[(size_t)PX * M1];         // [p][m]
__device__ float         g_lnbT[(size_t)PX * M1];
__device__ float         g_part[BB * 26 * 2];
__device__ float         g_stats[BB * 2];

// ---------------------------------------------------------------------------
// Helpers (base-ISA only: ldmatrix / mma.sync / cp.async)
// ---------------------------------------------------------------------------
__device__ __forceinline__ uint32_t smem_u32(const void* p) {
    uint32_t a;
    asm("{ .reg .u64 t; cvta.to.shared.u64 t, %1; cvt.u32.u64 %0, t; }"
        : "=r"(a) : "l"(p));
    return a;
}
#define SW128(o) ((o) ^ (((o) >> 3) & 0x70))

__device__ __forceinline__ void sts128(uint32_t a, uint4 v) {
    asm volatile("st.shared.v4.b32 [%0], {%1,%2,%3,%4};"
                 :: "r"(a), "r"(v.x), "r"(v.y), "r"(v.z), "r"(v.w) : "memory");
}
__device__ __forceinline__ void cp16(uint32_t dst, const void* src) {
    asm volatile("cp.async.cg.shared.global [%0], [%1], 16;"
                 :: "r"(dst), "l"(src) : "memory");
}
#define CP_COMMIT() asm volatile("cp.async.commit_group;" ::: "memory")
#define CP_WAIT(n)  asm volatile("cp.async.wait_group %0;" :: "n"(n) : "memory")

__device__ __forceinline__ void ldm_x4(uint32_t addr, uint32_t& r0, uint32_t& r1,
                                       uint32_t& r2, uint32_t& r3) {
    asm volatile("ldmatrix.sync.aligned.m8n8.x4.shared.b16 {%0,%1,%2,%3}, [%4];"
                 : "=r"(r0), "=r"(r1), "=r"(r2), "=r"(r3) : "r"(addr));
}
__device__ __forceinline__ void mma_bf16(float* c, const uint32_t* a,
                                         uint32_t b0, uint32_t b1) {
    asm volatile(
        "mma.sync.aligned.m16n8k16.row.col.f32.bf16.bf16.f32 "
        "{%0,%1,%2,%3},{%4,%5,%6,%7},{%8,%9},{%0,%1,%2,%3};"
        : "+f"(c[0]), "+f"(c[1]), "+f"(c[2]), "+f"(c[3])
        : "r"(a[0]), "r"(a[1]), "r"(a[2]), "r"(a[3]), "r"(b0), "r"(b1));
}

__device__ __forceinline__ void split_bf16(float v, __nv_bfloat16& h, __nv_bfloat16& l) {
    h = __float2bfloat16_rn(v);
    l = __float2bfloat16_rn(v - __bfloat162float(h));
}
__device__ __forceinline__ uint32_t pack2(__nv_bfloat16 a, __nv_bfloat16 b) {
    return (uint32_t)__bfloat16_as_ushort(a) | ((uint32_t)__bfloat16_as_ushort(b) << 16);
}

// ---------------------------------------------------------------------------
// Kernel 0: weight splits + ln transpose
// ---------------------------------------------------------------------------
constexpr int PREPW_TOTAL = M1 * K1 + CC * M1 + 2 * M1 * PX;

__global__ void prepw_kernel(const float* __restrict__ w1, const float* __restrict__ w2,
                             const float* __restrict__ lnw, const float* __restrict__ lnb) {
    int idx = blockIdx.x * blockDim.x + threadIdx.x;
    if (idx >= PREPW_TOTAL) return;
    if (idx < M1 * K1) {
        int m = idx / K1, k = idx % K1;
        __nv_bfloat16 h, l; split_bf16(w1[idx], h, l);
        g_w1s[m * KP + k] = h;
        g_w1s[m * KP + K1 + k] = l;
    } else if (idx < M1 * K1 + CC * M1) {
        int j = idx - M1 * K1;
        int m = j / M1, k = j % M1;
        __nv_bfloat16 h, l; split_bf16(w2[j], h, l);
        g_w2s[m * W2K + k] = h;
        g_w2s[m * W2K + M1 + k] = l;
    } else if (idx < M1 * K1 + CC * M1 + M1 * PX) {
        int j = idx - M1 * K1 - CC * M1;
        int p = j / M1, m = j % M1;
        g_lnwT[(size_t)p * M1 + m] = lnw[(size_t)m * PX + p];
    } else {
        int j = idx - M1 * K1 - CC * M1 - M1 * PX;
        int p = j / M1, m = j % M1;
        g_lnbT[(size_t)p * M1 + m] = lnb[(size_t)m * PX + p];
    }
}

// ---------------------------------------------------------------------------
// Kernel 1: perception + bf16 split, [b][px][hi192|lo192], zero pad rows
// ---------------------------------------------------------------------------
__global__ __launch_bounds__(256) void perc_kernel(const float* __restrict__ state) {
    __shared__ __nv_bfloat16 sp[32][KP];
    int b = blockIdx.y;
    int bx = blockIdx.x;
    int tid = threadIdx.x;

    if (bx >= 50) {  // pad rows 1600..1663 -> zeros
        int px0 = PX + (bx - 50) * 32;
        uint4 z = make_uint4(0, 0, 0, 0);
        uint4* dst = reinterpret_cast<uint4*>(g_perc + ((size_t)b * PXP + px0) * KP);
#pragma unroll
        for (int i = 0; i < 6; i++) dst[tid + i * 256] = z;
        return;
    }
    int px0 = bx * 32;
    int c  = tid & 63;
    int pq = tid >> 6;
    const float* s = state + ((size_t)b * CC + c) * PX;
#pragma unroll
    for (int i = 0; i < 8; i++) {
        int pl = pq * 8 + i;
        int p  = px0 + pl;
        int h = p / WW, w = p % WW;
        float v[3][3];
#pragma unroll
        for (int dy = -1; dy <= 1; dy++)
#pragma unroll
            for (int dx = -1; dx <= 1; dx++) {
                int hh = h + dy, ww2 = w + dx;
                v[dy + 1][dx + 1] =
                    (hh >= 0 && hh < HH && ww2 >= 0 && ww2 < WW) ? s[hh * WW + ww2] : 0.f;
            }
        float sx = -v[0][0] + v[0][2] - 2.f * v[1][0] + 2.f * v[1][2] - v[2][0] + v[2][2];
        float sy = -v[0][0] - 2.f * v[0][1] - v[0][2] + v[2][0] + 2.f * v[2][1] + v[2][2];
        float id = v[1][1];
        __nv_bfloat16 h0, l0, h1, l1, h2, l2;
        split_bf16(sx, h0, l0);
        split_bf16(sy, h1, l1);
        split_bf16(id, h2, l2);
        sp[pl][3 * c + 0] = h0;  sp[pl][K1 + 3 * c + 0] = l0;
        sp[pl][3 * c + 1] = h1;  sp[pl][K1 + 3 * c + 1] = l1;
        sp[pl][3 * c + 2] = h2;  sp[pl][K1 + 3 * c + 2] = l2;
    }
    __syncthreads();
    const uint4* src = reinterpret_cast<const uint4*>(&sp[0][0]);
    uint4* dst = reinterpret_cast<uint4*>(g_perc + ((size_t)b * PXP + px0) * KP);
#pragma unroll
    for (int i = 0; i < 6; i++) dst[tid + i * 256] = src[tid + i * 256];
}

// ---------------------------------------------------------------------------
// Kernel 2: GEMM1 (mma.sync bf16) Y[128px, 256mlp] tiles, K'=576 (9x64 chunks)
//   3-product split segments. Fused Y store + deterministic LN partials.
// ---------------------------------------------------------------------------
__constant__ int AOFF1[9] = {0, 64, 128, 0, 64, 128, 192, 256, 320};
__constant__ int BOFF1[9] = {0, 64, 128, 192, 256, 320, 0, 64, 128};

__global__ __launch_bounds__(512, 1) void gemm1_kernel() {
    extern __shared__ char dsm[];          // [2][16KB] A | [2][32KB] B
    __shared__ float red[512];
    uint32_t base = smem_u32(dsm);
    int tid = threadIdx.x;
    int lane = tid & 31, wid = tid >> 5;
    int nt = blockIdx.x;   // 0..1  (mlp half)
    int pt = blockIdx.y;   // 0..12 (px tile)
    int b  = blockIdx.z;

    const __nv_bfloat16* Ab = g_perc + ((size_t)b * PXP + pt * 128) * KP;
    const __nv_bfloat16* Bb = g_w1s + (size_t)(nt * 256) * KP;

    int m0 = (wid & 3) * 32;
    int n0 = (wid >> 2) * 64;
    int a_row  = m0 + (lane & 15);
    int a_byte = (lane >> 4) << 4;
    int qq     = lane >> 3;
    int b_row  = n0 + ((qq >> 1) << 3) + (lane & 7);
    int b_byte = (qq & 1) << 4;

    float acc[2][8][4] = {};

    // prologue: stage 0
    {
        uint32_t sA = base, sB = base + 32768;
#pragma unroll
        for (int i = 0; i < 2; i++) {
            int g = tid + i * 512, r = g >> 3, c = g & 7;
            cp16(sA + SW128(r * 128 + c * 16), Ab + (size_t)r * KP + 0 + c * 8);
        }
#pragma unroll
        for (int i = 0; i < 4; i++) {
            int g = tid + i * 512, r = g >> 3, c = g & 7;
            cp16(sB + SW128(r * 128 + c * 16), Bb + (size_t)r * KP + 0 + c * 8);
        }
        CP_COMMIT();
    }

    for (int ch = 0; ch < 9; ch++) {
        if (ch < 8) {
            int st = (ch + 1) & 1;
            int ao = AOFF1[ch + 1], bo = BOFF1[ch + 1];
            uint32_t sA = base + st * 16384, sB = base + 32768 + st * 32768;
#pragma unroll
            for (int i = 0; i < 2; i++) {
                int g = tid + i * 512, r = g >> 3, c = g & 7;
                cp16(sA + SW128(r * 128 + c * 16), Ab + (size_t)r * KP + ao + c * 8);
            }
#pragma unroll
            for (int i = 0; i < 4; i++) {
                int g = tid + i * 512, r = g >> 3, c = g & 7;
                cp16(sB + SW128(r * 128 + c * 16), Bb + (size_t)r * KP + bo + c * 8);
            }
            CP_COMMIT();
            CP_WAIT(1);
        } else {
            CP_WAIT(0);
        }
        __syncthreads();
        uint32_t sA = base + (ch & 1) * 16384;
        uint32_t sB = base + 32768 + (ch & 1) * 32768;
#pragma unroll
        for (int kk = 0; kk < 4; kk++) {
            int kb = kk * 32;
            uint32_t a[2][4];
#pragma unroll
            for (int mi = 0; mi < 2; mi++)
                ldm_x4(sA + SW128((a_row + mi * 16) * 128 + kb + a_byte),
                       a[mi][0], a[mi][1], a[mi][2], a[mi][3]);
            uint32_t bf[4][4];
#pragma unroll
            for (int n2 = 0; n2 < 4; n2++)
                ldm_x4(sB + SW128((b_row + n2 * 16) * 128 + kb + b_byte),
                       bf[n2][0], bf[n2][1], bf[n2][2], bf[n2][3]);
#pragma unroll
            for (int mi = 0; mi < 2; mi++)
#pragma unroll
                for (int ni = 0; ni < 8; ni++)
                    mma_bf16(acc[mi][ni], a[mi],
                             bf[ni >> 1][(ni & 1) * 2], bf[ni >> 1][(ni & 1) * 2 + 1]);
        }
        __syncthreads();
    }

    // epilogue: store Y + LN partial sums
    float s = 0.f, s2 = 0.f;
    size_t rbase = (size_t)b * PXP + pt * 128 + m0;
#pragma unroll
    for (int mi = 0; mi < 2; mi++)
#pragma unroll
        for (int ni = 0; ni < 8; ni++) {
            float* c = acc[mi][ni];
            s  += c[0] + c[1] + c[2] + c[3];
            s2 += c[0] * c[0] + c[1] * c[1] + c[2] * c[2] + c[3] * c[3];
            size_t row = rbase + mi * 16 + (lane >> 2);
            int col = nt * 256 + n0 + ni * 8 + (lane & 3) * 2;
            float* p = g_y + row * M1 + col;
            *reinterpret_cast<float2*>(p) = make_float2(c[0], c[1]);
            *reinterpret_cast<float2*>(p + 8 * M1) = make_float2(c[2], c[3]);
        }

    red[tid] = s;
    __syncthreads();
    for (int o = 256; o > 0; o >>= 1) {
        if (tid < o) red[tid] += red[tid + o];
        __syncthreads();
    }
    float bs = red[0];
    __syncthreads();
    red[tid] = s2;
    __syncthreads();
    for (int o = 256; o > 0; o >>= 1) {
        if (tid < o) red[tid] += red[tid + o];
        __syncthreads();
    }
    if (tid == 0) {
        int pi = (b * 13 + pt) * 2 + nt;
        g_part[pi * 2 + 0] = bs;
        g_part[pi * 2 + 1] = red[0];
    }
}

// ---------------------------------------------------------------------------
// Kernel 3: per-sample LN stats (deterministic fixed order)
// ---------------------------------------------------------------------------
__global__ void stats_kernel() {
    int b = threadIdx.x;
    if (b >= BB) return;
    float s = 0.f, s2 = 0.f;
    for (int i = 0; i < 26; i++) {
        s  += g_part[(b * 26 + i) * 2 + 0];
        s2 += g_part[(b * 26 + i) * 2 + 1];
    }
    float inv = 1.f / (float)(M1 * PX);
    float mu  = s * inv;
    float var = s2 * inv - mu * mu;
    g_stats[b * 2 + 0] = mu;
    g_stats[b * 2 + 1] = rsqrtf(var + LN_EPS);
}

// ---------------------------------------------------------------------------
// Kernel 4: GEMM2 (mma.sync bf16) Z[128px,64c] = relu(LN(Y))_split @ w2_split^T
//   LN+ReLU+split fused into A-tile build; fused mask/alive/residual epilogue.
// ---------------------------------------------------------------------------
__global__ __launch_bounds__(256) void gemm2_kernel(
    const float* __restrict__ state, const int* __restrict__ mask,
    float* __restrict__ out) {
    extern __shared__ char dsm[];   // Ah 16K | Al 16K | Bh 8K | Bl 8K
    __shared__ float scl[128];
    uint32_t sAh = smem_u32(dsm);
    uint32_t sAl = sAh + 16384;
    uint32_t sBh = sAh + 32768;
    uint32_t sBl = sAh + 40960;

    int tid = threadIdx.x, lane = tid & 31, wid = tid >> 5;
    int pt = blockIdx.x;
    int b  = blockIdx.y;

    float mu   = g_stats[b * 2 + 0];
    float rstd = g_stats[b * 2 + 1];

    if (tid < 128) {
        int p = pt * 128 + tid;
        float sc = 0.f;
        if (p < PX) {
            int h = p / WW, w = p % WW;
            const float* alive = state + ((size_t)b * CC + 3) * PX;
            float mx = -1e30f;
#pragma unroll
            for (int dy = -1; dy <= 1; dy++)
#pragma unroll
                for (int dx = -1; dx <= 1; dx++) {
                    int hh = h + dy, ww2 = w + dx;
                    if (hh >= 0 && hh < HH && ww2 >= 0 && ww2 < WW)
                        mx = fmaxf(mx, alive[hh * WW + ww2]);
                }
            sc = (mx > 0.1f ? 1.f : 0.f) * (float)mask[p];
        }
        scl[tid] = sc;
    }

    int m0 = (wid & 3) * 32;
    int n0 = (wid >> 2) * 32;
    int a_row  = m0 + (lane & 15);
    int a_byte = (lane >> 4) << 4;
    int qq     = lane >> 3;
    int b_row  = n0 + ((qq >> 1) << 3) + (lane & 7);
    int b_byte = (qq & 1) << 4;

    float acc[2][4][4] = {};

    for (int ch = 0; ch < 8; ch++) {
        int c0 = ch * 64;
        __syncthreads();   // prev mma done before overwriting tiles
        // B tiles via cp.async (overlaps the z-compute LDGs below)
#pragma unroll
        for (int i = 0; i < 2; i++) {
            int g = tid + i * 256, r = g >> 3, c = g & 7;
            cp16(sBh + SW128(r * 128 + c * 16), g_w2s + (size_t)r * W2K + c0 + c * 8);
            cp16(sBl + SW128(r * 128 + c * 16), g_w2s + (size_t)r * W2K + M1 + c0 + c * 8);
        }
        CP_COMMIT();
        // A tiles: y -> LN -> ReLU -> split -> Ah/Al
#pragma unroll
        for (int i = 0; i < 4; i++) {
            int g = tid + i * 256, r = g >> 3, c = g & 7;
            int px = pt * 128 + r;
            float z[8];
            if (px < PX) {
                const float* yp = g_y   + ((size_t)b * PXP + px) * M1 + c0 + c * 8;
                const float* wp = g_lnwT + (size_t)px * M1 + c0 + c * 8;
                const float* bp = g_lnbT + (size_t)px * M1 + c0 + c * 8;
#pragma unroll
                for (int q2 = 0; q2 < 2; q2++) {
                    float4 y = *reinterpret_cast<const float4*>(yp + q2 * 4);
                    float4 w = *reinterpret_cast<const float4*>(wp + q2 * 4);
                    float4 bb = *reinterpret_cast<const float4*>(bp + q2 * 4);
                    z[q2 * 4 + 0] = fmaxf((y.x - mu) * rstd * w.x + bb.x, 0.f);
                    z[q2 * 4 + 1] = fmaxf((y.y - mu) * rstd * w.y + bb.y, 0.f);
                    z[q2 * 4 + 2] = fmaxf((y.z - mu) * rstd * w.z + bb.z, 0.f);
                    z[q2 * 4 + 3] = fmaxf((y.w - mu) * rstd * w.w + bb.w, 0.f);
                }
            } else {
#pragma unroll
                for (int q2 = 0; q2 < 8; q2++) z[q2] = 0.f;
            }
            __nv_bfloat16 h[8], l[8];
#pragma unroll
            for (int q2 = 0; q2 < 8; q2++) split_bf16(z[q2], h[q2], l[q2]);
            sts128(sAh + SW128(r * 128 + c * 16),
                   make_uint4(pack2(h[0], h[1]), pack2(h[2], h[3]),
                              pack2(h[4], h[5]), pack2(h[6], h[7])));
            sts128(sAl + SW128(r * 128 + c * 16),
                   make_uint4(pack2(l[0], l[1]), pack2(l[2], l[3]),
                              pack2(l[4], l[5]), pack2(l[6], l[7])));
        }
        CP_WAIT(0);
        __syncthreads();
        // 3 split products: (Ah,Bh), (Ah,Bl), (Al,Bh)
#pragma unroll
        for (int pass = 0; pass < 3; pass++) {
            uint32_t sa = (pass == 2) ? sAl : sAh;
            uint32_t sb = (pass == 1) ? sBl : sBh;
#pragma unroll
            for (int kk = 0; kk < 4; kk++) {
                int kb = kk * 32;
                uint32_t a[2][4];
#pragma unroll
                for (int mi = 0; mi < 2; mi++)
                    ldm_x4(sa + SW128((a_row + mi * 16) * 128 + kb + a_byte),
                           a[mi][0], a[mi][1], a[mi][2], a[mi][3]);
                uint32_t bf[2][4];
#pragma unroll
                for (int n2 = 0; n2 < 2; n2++)
                    ldm_x4(sb + SW128((b_row + n2 * 16) * 128 + kb + b_byte),
                           bf[n2][0], bf[n2][1], bf[n2][2], bf[n2][3]);
#pragma unroll
                for (int mi = 0; mi < 2; mi++)
#pragma unroll
                    for (int ni = 0; ni < 4; ni++)
                        mma_bf16(acc[mi][ni], a[mi],
                                 bf[ni >> 1][(ni & 1) * 2], bf[ni >> 1][(ni & 1) * 2 + 1]);
            }
        }
    }

    // epilogue: out[b][c][px] = state + z * scl
#pragma unroll
    for (int mi = 0; mi < 2; mi++)
#pragma unroll
        for (int ni = 0; ni < 4; ni++) {
            int rl0 = m0 + mi * 16 + (lane >> 2);
            int cc  = n0 + ni * 8 + (lane & 3) * 2;
#pragma unroll
            for (int hf = 0; hf < 2; hf++) {
                int rl = rl0 + hf * 8;
                int px = pt * 128 + rl;
                if (px < PX) {
                    float sc = scl[rl];
                    size_t o0 = ((size_t)b * CC + cc) * PX + px;
                    out[o0]      = state[o0]      + acc[mi][ni][hf * 2 + 0] * sc;
                    out[o0 + PX] = state[o0 + PX] + acc[mi][ni][hf * 2 + 1] * sc;
                }
            }
        }
}

// ---------------------------------------------------------------------------
extern "C" void kernel_launch(void* const* d_in, const int* in_sizes, int n_in,
                              void* d_out, int out_size) {
    const float* state = (const float*)d_in[0];
    const float* w1    = (const float*)d_in[1];
    const float* lnw   = (const float*)d_in[2];
    const float* lnb   = (const float*)d_in[3];
    const float* w2    = (const float*)d_in[4];
    const int*   mask  = (const int*)d_in[5];
    float* out = (float*)d_out;

    cudaFuncSetAttribute(gemm1_kernel, cudaFuncAttributeMaxDynamicSharedMemorySize, 98304);
    cudaFuncSetAttribute(gemm2_kernel, cudaFuncAttributeMaxDynamicSharedMemorySize, 49152);

    prepw_kernel<<<(PREPW_TOTAL + 255) / 256, 256>>>(w1, w2, lnw, lnb);
    perc_kernel<<<dim3(52, BB), 256>>>(state);
    gemm1_kernel<<<dim3(2, 13, BB), 512, 98304>>>();
    stats_kernel<<<1, 128>>>();
    gemm2_kernel<<<dim3(13, BB), 256, 49152>>>(state, mask, out);
}

// round 5
// speedup vs baseline: 1.2752x; 1.2273x over previous
#include <cuda_runtime.h>
#include <cuda_bf16.h>
#include <cstdint>

// ---------------------------------------------------------------------------
// Problem constants
// ---------------------------------------------------------------------------
constexpr int BB   = 128;
constexpr int CC   = 64;
constexpr int K1   = 192;    // 3*C perception channels
constexpr int M1   = 512;    // MLP dim
constexpr int HH   = 40;
constexpr int WW   = 40;
constexpr int PX   = 1600;   // H*W
constexpr int PXP  = 1664;   // padded to 26*64
constexpr float LN_EPS = 1e-5f;

constexpr int KP   = 384;    // perc row: [hi(192) | lo(192)] bf16
constexpr int W2K  = 1024;   // w2split row: [hi(512) | lo(512)] bf16

// ---------------------------------------------------------------------------
// Device scratch
// ---------------------------------------------------------------------------
__device__ __nv_bfloat16 g_perc[(size_t)BB * PXP * KP];   // 163 MB
__device__ float         g_y[(size_t)BB * PXP * M1];      // 436 MB (compacted rows)
__device__ __nv_bfloat16 g_w1s[M1 * KP];                  // [512][384]
__device__ __nv_bfloat16 g_w2s[CC * W2K];                 // [64][1024]
__device__ float         g_lnwT[(size_t)PX * M1];         // [p][m]
__device__ float         g_lnbT[(size_t)PX * M1];
__device__ float         g_part[BB * 52 * 2];
__device__ float         g_stats[BB * 2];
__device__ int           g_plist[PX];                     // compacted px list
__device__ int           g_cidx[PX];                      // px -> compact idx or -1
__device__ int           g_cnt;

// ---------------------------------------------------------------------------
// Helpers (base-ISA only: ldmatrix / mma.sync / cp.async)
// ---------------------------------------------------------------------------
__device__ __forceinline__ uint32_t smem_u32(const void* p) {
    uint32_t a;
    asm("{ .reg .u64 t; cvta.to.shared.u64 t, %1; cvt.u32.u64 %0, t; }"
        : "=r"(a) : "l"(p));
    return a;
}
#define SW128(o) ((o) ^ (((o) >> 3) & 0x70))

__device__ __forceinline__ void sts128(uint32_t a, uint4 v) {
    asm volatile("st.shared.v4.b32 [%0], {%1,%2,%3,%4};"
                 :: "r"(a), "r"(v.x), "r"(v.y), "r"(v.z), "r"(v.w) : "memory");
}
__device__ __forceinline__ void cp16(uint32_t dst, const void* src) {
    asm volatile("cp.async.cg.shared.global [%0], [%1], 16;"
                 :: "r"(dst), "l"(src) : "memory");
}
#define CP_COMMIT() asm volatile("cp.async.commit_group;" ::: "memory")
#define CP_WAIT(n)  asm volatile("cp.async.wait_group %0;" :: "n"(n) : "memory")

__device__ __forceinline__ void ldm_x4(uint32_t addr, uint32_t& r0, uint32_t& r1,
                                       uint32_t& r2, uint32_t& r3) {
    asm volatile("ldmatrix.sync.aligned.m8n8.x4.shared.b16 {%0,%1,%2,%3}, [%4];"
                 : "=r"(r0), "=r"(r1), "=r"(r2), "=r"(r3) : "r"(addr));
}
__device__ __forceinline__ void mma_bf16(float* c, const uint32_t* a,
                                         uint32_t b0, uint32_t b1) {
    asm volatile(
        "mma.sync.aligned.m16n8k16.row.col.f32.bf16.bf16.f32 "
        "{%0,%1,%2,%3},{%4,%5,%6,%7},{%8,%9},{%0,%1,%2,%3};"
        : "+f"(c[0]), "+f"(c[1]), "+f"(c[2]), "+f"(c[3])
        : "r"(a[0]), "r"(a[1]), "r"(a[2]), "r"(a[3]), "r"(b0), "r"(b1));
}

__device__ __forceinline__ void split_bf16(float v, __nv_bfloat16& h, __nv_bfloat16& l) {
    h = __float2bfloat16_rn(v);
    l = __float2bfloat16_rn(v - __bfloat162float(h));
}
__device__ __forceinline__ uint32_t pack2(__nv_bfloat16 a, __nv_bfloat16 b) {
    return (uint32_t)__bfloat16_as_ushort(a) | ((uint32_t)__bfloat16_as_ushort(b) << 16);
}

// ---------------------------------------------------------------------------
// Kernel 0a: weight splits + ln transpose
// ---------------------------------------------------------------------------
constexpr int PREPW_TOTAL = M1 * K1 + CC * M1 + 2 * M1 * PX;

__global__ void prepw_kernel(const float* __restrict__ w1, const float* __restrict__ w2,
                             const float* __restrict__ lnw, const float* __restrict__ lnb) {
    int idx = blockIdx.x * blockDim.x + threadIdx.x;
    if (idx >= PREPW_TOTAL) return;
    if (idx < M1 * K1) {
        int m = idx / K1, k = idx % K1;
        __nv_bfloat16 h, l; split_bf16(w1[idx], h, l);
        g_w1s[m * KP + k] = h;
        g_w1s[m * KP + K1 + k] = l;
    } else if (idx < M1 * K1 + CC * M1) {
        int j = idx - M1 * K1;
        int m = j / M1, k = j % M1;
        __nv_bfloat16 h, l; split_bf16(w2[j], h, l);
        g_w2s[m * W2K + k] = h;
        g_w2s[m * W2K + M1 + k] = l;
    } else if (idx < M1 * K1 + CC * M1 + M1 * PX) {
        int j = idx - M1 * K1 - CC * M1;
        int p = j / M1, m = j % M1;
        g_lnwT[(size_t)p * M1 + m] = lnw[(size_t)m * PX + p];
    } else {
        int j = idx - M1 * K1 - CC * M1 - M1 * PX;
        int p = j / M1, m = j % M1;
        g_lnbT[(size_t)p * M1 + m] = lnb[(size_t)m * PX + p];
    }
}

// ---------------------------------------------------------------------------
// Kernel 0b: mask compaction (deterministic order)
// ---------------------------------------------------------------------------
__global__ void compact_kernel(const int* __restrict__ mask) {
    __shared__ int sm[PX];
    int tid = threadIdx.x;
    for (int i = tid; i < PX; i += 256) sm[i] = mask[i];
    __syncthreads();
    if (tid == 0) {
        int c = 0;
        for (int p = 0; p < PX; p++) {
            if (sm[p] != 0) { g_plist[c] = p; g_cidx[p] = c; c++; }
            else            { g_cidx[p] = -1; }
        }
        g_cnt = c;
    }
}

// ---------------------------------------------------------------------------
// Kernel 0c: out = state (masked-off pixels keep state unchanged)
// ---------------------------------------------------------------------------
__global__ void outinit_kernel(const float* __restrict__ state, float* __restrict__ out) {
    size_t i = (size_t)blockIdx.x * blockDim.x + threadIdx.x;
    const float4* s = reinterpret_cast<const float4*>(state);
    float4* o = reinterpret_cast<float4*>(out);
    size_t n4 = (size_t)BB * CC * PX / 4;
    if (i < n4) o[i] = s[i];
}

// ---------------------------------------------------------------------------
// Kernel 1: perception + bf16 split, [b][px][hi192|lo192], zero pad rows
// ---------------------------------------------------------------------------
__global__ __launch_bounds__(256) void perc_kernel(const float* __restrict__ state) {
    __shared__ __nv_bfloat16 sp[32][KP];
    int b = blockIdx.y;
    int bx = blockIdx.x;
    int tid = threadIdx.x;

    if (bx >= 50) {  // pad rows 1600..1663 -> zeros
        int px0 = PX + (bx - 50) * 32;
        uint4 z = make_uint4(0, 0, 0, 0);
        uint4* dst = reinterpret_cast<uint4*>(g_perc + ((size_t)b * PXP + px0) * KP);
#pragma unroll
        for (int i = 0; i < 6; i++) dst[tid + i * 256] = z;
        return;
    }
    int px0 = bx * 32;
    int c  = tid & 63;
    int pq = tid >> 6;
    const float* s = state + ((size_t)b * CC + c) * PX;
#pragma unroll
    for (int i = 0; i < 8; i++) {
        int pl = pq * 8 + i;
        int p  = px0 + pl;
        int h = p / WW, w = p % WW;
        float v[3][3];
#pragma unroll
        for (int dy = -1; dy <= 1; dy++)
#pragma unroll
            for (int dx = -1; dx <= 1; dx++) {
                int hh = h + dy, ww2 = w + dx;
                v[dy + 1][dx + 1] =
                    (hh >= 0 && hh < HH && ww2 >= 0 && ww2 < WW) ? s[hh * WW + ww2] : 0.f;
            }
        float sx = -v[0][0] + v[0][2] - 2.f * v[1][0] + 2.f * v[1][2] - v[2][0] + v[2][2];
        float sy = -v[0][0] - 2.f * v[0][1] - v[0][2] + v[2][0] + 2.f * v[2][1] + v[2][2];
        float id = v[1][1];
        __nv_bfloat16 h0, l0, h1, l1, h2, l2;
        split_bf16(sx, h0, l0);
        split_bf16(sy, h1, l1);
        split_bf16(id, h2, l2);
        sp[pl][3 * c + 0] = h0;  sp[pl][K1 + 3 * c + 0] = l0;
        sp[pl][3 * c + 1] = h1;  sp[pl][K1 + 3 * c + 1] = l1;
        sp[pl][3 * c + 2] = h2;  sp[pl][K1 + 3 * c + 2] = l2;
    }
    __syncthreads();
    const uint4* src = reinterpret_cast<const uint4*>(&sp[0][0]);
    uint4* dst = reinterpret_cast<uint4*>(g_perc + ((size_t)b * PXP + px0) * KP);
#pragma unroll
    for (int i = 0; i < 6; i++) dst[tid + i * 256] = src[tid + i * 256];
}

// ---------------------------------------------------------------------------
// Kernel 2: GEMM1 (mma.sync bf16) tiles 64px x 256mlp, K'=576 (9x64 chunks).
//   256 threads, 80KB smem (2 CTAs/SM). Stats over all px; y stored only for
//   masked px (compact row index).
// ---------------------------------------------------------------------------
__constant__ int AOFF1[9] = {0, 64, 128, 0, 64, 128, 192, 256, 320};
__constant__ int BOFF1[9] = {0, 64, 128, 192, 256, 320, 0, 64, 128};

__global__ __launch_bounds__(256) void gemm1_kernel() {
    extern __shared__ char dsm[];   // per stage: A 8KB | B 32KB; 2 stages = 80KB
    __shared__ float red[256];
    uint32_t base = smem_u32(dsm);
    int tid = threadIdx.x;
    int lane = tid & 31, wid = tid >> 5;
    int nt = blockIdx.x;   // 0..1  (mlp half)
    int pt = blockIdx.y;   // 0..25 (px tile of 64)
    int b  = blockIdx.z;

    const __nv_bfloat16* Ab = g_perc + ((size_t)b * PXP + pt * 64) * KP;
    const __nv_bfloat16* Bb = g_w1s + (size_t)(nt * 256) * KP;

    int m0 = (wid & 1) * 32;
    int n0 = (wid >> 1) * 64;
    int a_row  = m0 + (lane & 15);
    int a_byte = (lane >> 4) << 4;
    int qq     = lane >> 3;
    int b_row  = n0 + ((qq >> 1) << 3) + (lane & 7);
    int b_byte = (qq & 1) << 4;

    float acc[2][8][4] = {};

    // prologue: stage 0
    {
        uint32_t sA = base, sB = base + 8192;
#pragma unroll
        for (int i = 0; i < 2; i++) {
            int g = tid + i * 256, r = g >> 3, c = g & 7;
            cp16(sA + SW128(r * 128 + c * 16), Ab + (size_t)r * KP + 0 + c * 8);
        }
#pragma unroll
        for (int i = 0; i < 8; i++) {
            int g = tid + i * 256, r = g >> 3, c = g & 7;
            cp16(sB + SW128(r * 128 + c * 16), Bb + (size_t)r * KP + 0 + c * 8);
        }
        CP_COMMIT();
    }

    for (int ch = 0; ch < 9; ch++) {
        if (ch < 8) {
            int st = (ch + 1) & 1;
            int ao = AOFF1[ch + 1], bo = BOFF1[ch + 1];
            uint32_t sA = base + st * 40960, sB = sA + 8192;
#pragma unroll
            for (int i = 0; i < 2; i++) {
                int g = tid + i * 256, r = g >> 3, c = g & 7;
                cp16(sA + SW128(r * 128 + c * 16), Ab + (size_t)r * KP + ao + c * 8);
            }
#pragma unroll
            for (int i = 0; i < 8; i++) {
                int g = tid + i * 256, r = g >> 3, c = g & 7;
                cp16(sB + SW128(r * 128 + c * 16), Bb + (size_t)r * KP + bo + c * 8);
            }
            CP_COMMIT();
            CP_WAIT(1);
        } else {
            CP_WAIT(0);
        }
        __syncthreads();
        uint32_t sA = base + (ch & 1) * 40960;
        uint32_t sB = sA + 8192;
#pragma unroll
        for (int kk = 0; kk < 4; kk++) {
            int kb = kk * 32;
            uint32_t a[2][4];
#pragma unroll
            for (int mi = 0; mi < 2; mi++)
                ldm_x4(sA + SW128((a_row + mi * 16) * 128 + kb + a_byte),
                       a[mi][0], a[mi][1], a[mi][2], a[mi][3]);
            uint32_t bf[4][4];
#pragma unroll
            for (int n2 = 0; n2 < 4; n2++)
                ldm_x4(sB + SW128((b_row + n2 * 16) * 128 + kb + b_byte),
                       bf[n2][0], bf[n2][1], bf[n2][2], bf[n2][3]);
#pragma unroll
            for (int mi = 0; mi < 2; mi++)
#pragma unroll
                for (int ni = 0; ni < 8; ni++)
                    mma_bf16(acc[mi][ni], a[mi],
                             bf[ni >> 1][(ni & 1) * 2], bf[ni >> 1][(ni & 1) * 2 + 1]);
        }
        __syncthreads();
    }

    // epilogue: stats over all, y stored only for masked px (compacted row)
    float s = 0.f, s2 = 0.f;
#pragma unroll
    for (int mi = 0; mi < 2; mi++)
#pragma unroll
        for (int ni = 0; ni < 8; ni++) {
            float* c = acc[mi][ni];
            s  += c[0] + c[1] + c[2] + c[3];
            s2 += c[0] * c[0] + c[1] * c[1] + c[2] * c[2] + c[3] * c[3];
        }
#pragma unroll
    for (int mi = 0; mi < 2; mi++)
#pragma unroll
        for (int half = 0; half < 2; half++) {
            int r  = m0 + mi * 16 + (lane >> 2) + half * 8;
            int px = pt * 64 + r;
            int ci = (px < PX) ? g_cidx[px] : -1;
            if (ci >= 0) {
                float* rowp = g_y + ((size_t)b * PXP + ci) * M1
                              + nt * 256 + n0 + (lane & 3) * 2;
#pragma unroll
                for (int ni = 0; ni < 8; ni++)
                    *reinterpret_cast<float2*>(rowp + ni * 8) =
                        make_float2(acc[mi][ni][half * 2], acc[mi][ni][half * 2 + 1]);
            }
        }

    red[tid] = s;
    __syncthreads();
    for (int o = 128; o > 0; o >>= 1) {
        if (tid < o) red[tid] += red[tid + o];
        __syncthreads();
    }
    float bs = red[0];
    __syncthreads();
    red[tid] = s2;
    __syncthreads();
    for (int o = 128; o > 0; o >>= 1) {
        if (tid < o) red[tid] += red[tid + o];
        __syncthreads();
    }
    if (tid == 0) {
        int pi = (b * 26 + pt) * 2 + nt;
        g_part[pi * 2 + 0] = bs;
        g_part[pi * 2 + 1] = red[0];
    }
}

// ---------------------------------------------------------------------------
// Kernel 3: per-sample LN stats (deterministic fixed order)
// ---------------------------------------------------------------------------
__global__ void stats_kernel() {
    int b = threadIdx.x;
    if (b >= BB) return;
    float s = 0.f, s2 = 0.f;
    for (int i = 0; i < 52; i++) {
        s  += g_part[(b * 52 + i) * 2 + 0];
        s2 += g_part[(b * 52 + i) * 2 + 1];
    }
    float inv = 1.f / (float)(M1 * PX);
    float mu  = s * inv;
    float var = s2 * inv - mu * mu;
    g_stats[b * 2 + 0] = mu;
    g_stats[b * 2 + 1] = rsqrtf(var + LN_EPS);
}

// ---------------------------------------------------------------------------
// Kernel 4: GEMM2 over COMPACTED pixels. Z[128cp,64c] = relu(LN(Y)) @ w2^T
//   (3-product split, merged k-loop). Fused alive/residual scatter epilogue.
// ---------------------------------------------------------------------------
__global__ __launch_bounds__(256) void gemm2_kernel(
    const float* __restrict__ state, float* __restrict__ out) {
    extern __shared__ char dsm[];   // Ah 16K | Al 16K | Bh 8K | Bl 8K = 48KB
    __shared__ float scl[128];
    __shared__ int   spx[128];
    uint32_t sAh = smem_u32(dsm);
    uint32_t sAl = sAh + 16384;
    uint32_t sBh = sAh + 32768;
    uint32_t sBl = sAh + 40960;

    int cnt = g_cnt;
    int ct = blockIdx.x;
    if (ct * 128 >= cnt) return;
    int b  = blockIdx.y;

    int tid = threadIdx.x, lane = tid & 31, wid = tid >> 5;
    float mu   = g_stats[b * 2 + 0];
    float rstd = g_stats[b * 2 + 1];

    if (tid < 128) {
        int cp = ct * 128 + tid;
        float sc = 0.f;
        int px = 0;
        if (cp < cnt) {
            px = g_plist[cp];
            int h = px / WW, w = px % WW;
            const float* alive = state + ((size_t)b * CC + 3) * PX;
            float mx = -1e30f;
#pragma unroll
            for (int dy = -1; dy <= 1; dy++)
#pragma unroll
                for (int dx = -1; dx <= 1; dx++) {
                    int hh = h + dy, ww2 = w + dx;
                    if (hh >= 0 && hh < HH && ww2 >= 0 && ww2 < WW)
                        mx = fmaxf(mx, alive[hh * WW + ww2]);
                }
            sc = (mx > 0.1f) ? 1.f : 0.f;   // mask==1 guaranteed on compacted px
        }
        scl[tid] = sc;
        spx[tid] = px;
    }

    int m0 = (wid & 3) * 32;
    int n0 = (wid >> 2) * 32;
    int a_row  = m0 + (lane & 15);
    int a_byte = (lane >> 4) << 4;
    int qq     = lane >> 3;
    int b_row  = n0 + ((qq >> 1) << 3) + (lane & 7);
    int b_byte = (qq & 1) << 4;

    float acc[2][4][4] = {};

    for (int ch = 0; ch < 8; ch++) {
        int c0 = ch * 64;
        __syncthreads();   // prev mma done before overwriting tiles
#pragma unroll
        for (int i = 0; i < 2; i++) {
            int g = tid + i * 256, r = g >> 3, c = g & 7;
            cp16(sBh + SW128(r * 128 + c * 16), g_w2s + (size_t)r * W2K + c0 + c * 8);
            cp16(sBl + SW128(r * 128 + c * 16), g_w2s + (size_t)r * W2K + M1 + c0 + c * 8);
        }
        CP_COMMIT();
        // A tiles: gathered y -> LN -> ReLU -> split -> Ah/Al
#pragma unroll
        for (int i = 0; i < 4; i++) {
            int g = tid + i * 256, r = g >> 3, c = g & 7;
            int cp = ct * 128 + r;
            float z[8];
            if (cp < cnt) {
                int px = spx[r];
                const float* yp = g_y   + ((size_t)b * PXP + cp) * M1 + c0 + c * 8;
                const float* wp = g_lnwT + (size_t)px * M1 + c0 + c * 8;
                const float* bp = g_lnbT + (size_t)px * M1 + c0 + c * 8;
#pragma unroll
                for (int q2 = 0; q2 < 2; q2++) {
                    float4 y = *reinterpret_cast<const float4*>(yp + q2 * 4);
                    float4 w = *reinterpret_cast<const float4*>(wp + q2 * 4);
                    float4 bb = *reinterpret_cast<const float4*>(bp + q2 * 4);
                    z[q2 * 4 + 0] = fmaxf((y.x - mu) * rstd * w.x + bb.x, 0.f);
                    z[q2 * 4 + 1] = fmaxf((y.y - mu) * rstd * w.y + bb.y, 0.f);
                    z[q2 * 4 + 2] = fmaxf((y.z - mu) * rstd * w.z + bb.z, 0.f);
                    z[q2 * 4 + 3] = fmaxf((y.w - mu) * rstd * w.w + bb.w, 0.f);
                }
            } else {
#pragma unroll
                for (int q2 = 0; q2 < 8; q2++) z[q2] = 0.f;
            }
            __nv_bfloat16 h[8], l[8];
#pragma unroll
            for (int q2 = 0; q2 < 8; q2++) split_bf16(z[q2], h[q2], l[q2]);
            sts128(sAh + SW128(r * 128 + c * 16),
                   make_uint4(pack2(h[0], h[1]), pack2(h[2], h[3]),
                              pack2(h[4], h[5]), pack2(h[6], h[7])));
            sts128(sAl + SW128(r * 128 + c * 16),
                   make_uint4(pack2(l[0], l[1]), pack2(l[2], l[3]),
                              pack2(l[4], l[5]), pack2(l[6], l[7])));
        }
        CP_WAIT(0);
        __syncthreads();
        // merged k-loop: frags loaded once, 3 split products
#pragma unroll
        for (int kk = 0; kk < 4; kk++) {
            int kb = kk * 32;
            uint32_t ah[2][4], al[2][4];
#pragma unroll
            for (int mi = 0; mi < 2; mi++) {
                ldm_x4(sAh + SW128((a_row + mi * 16) * 128 + kb + a_byte),
                       ah[mi][0], ah[mi][1], ah[mi][2], ah[mi][3]);
                ldm_x4(sAl + SW128((a_row + mi * 16) * 128 + kb + a_byte),
                       al[mi][0], al[mi][1], al[mi][2], al[mi][3]);
            }
            uint32_t bh[2][4], bl[2][4];
#pragma unroll
            for (int n2 = 0; n2 < 2; n2++) {
                ldm_x4(sBh + SW128((b_row + n2 * 16) * 128 + kb + b_byte),
                       bh[n2][0], bh[n2][1], bh[n2][2], bh[n2][3]);
                ldm_x4(sBl + SW128((b_row + n2 * 16) * 128 + kb + b_byte),
                       bl[n2][0], bl[n2][1], bl[n2][2], bl[n2][3]);
            }
#pragma unroll
            for (int mi = 0; mi < 2; mi++)
#pragma unroll
                for (int ni = 0; ni < 4; ni++) {
                    int n2 = ni >> 1, rr = (ni & 1) * 2;
                    mma_bf16(acc[mi][ni], ah[mi], bh[n2][rr], bh[n2][rr + 1]);
                    mma_bf16(acc[mi][ni], ah[mi], bl[n2][rr], bl[n2][rr + 1]);
                    mma_bf16(acc[mi][ni], al[mi], bh[n2][rr], bh[n2][rr + 1]);
                }
        }
    }

    // epilogue: scatter out[b][c][px] = state + z * scl for compacted px
#pragma unroll
    for (int mi = 0; mi < 2; mi++)
#pragma unroll
        for (int ni = 0; ni < 4; ni++) {
            int rl0 = m0 + mi * 16 + (lane >> 2);
            int cc  = n0 + ni * 8 + (lane & 3) * 2;
#pragma unroll
            for (int hf = 0; hf < 2; hf++) {
                int rl = rl0 + hf * 8;
                int cp = ct * 128 + rl;
                if (cp < cnt) {
                    int px = spx[rl];
                    float sc = scl[rl];
                    size_t o0 = ((size_t)b * CC + cc) * PX + px;
                    out[o0]      = state[o0]      + acc[mi][ni][hf * 2 + 0] * sc;
                    out[o0 + PX] = state[o0 + PX] + acc[mi][ni][hf * 2 + 1] * sc;
                }
            }
        }
}

// ---------------------------------------------------------------------------
extern "C" void kernel_launch(void* const* d_in, const int* in_sizes, int n_in,
                              void* d_out, int out_size) {
    const float* state = (const float*)d_in[0];
    const float* w1    = (const float*)d_in[1];
    const float* lnw   = (const float*)d_in[2];
    const float* lnb   = (const float*)d_in[3];
    const float* w2    = (const float*)d_in[4];
    const int*   mask  = (const int*)d_in[5];
    float* out = (float*)d_out;

    cudaFuncSetAttribute(gemm1_kernel, cudaFuncAttributeMaxDynamicSharedMemorySize, 81920);
    cudaFuncSetAttribute(gemm2_kernel, cudaFuncAttributeMaxDynamicSharedMemorySize, 49152);

    prepw_kernel<<<(PREPW_TOTAL + 255) / 256, 256>>>(w1, w2, lnw, lnb);
    compact_kernel<<<1, 256>>>(mask);
    outinit_kernel<<<(BB * CC * PX / 4 + 255) / 256, 256>>>(state, out);
    perc_kernel<<<dim3(52, BB), 256>>>(state);
    gemm1_kernel<<<dim3(2, 26, BB), 256, 81920>>>();
    stats_kernel<<<1, 128>>>();
    gemm2_kernel<<<dim3(13, BB), 256, 49152>>>(state, out);
}

// round 6
// speedup vs baseline: 2.2930x; 1.7982x over previous
#include <cuda_runtime.h>
#include <cuda_bf16.h>
#include <cstdint>

// ---------------------------------------------------------------------------
// Problem constants
// ---------------------------------------------------------------------------
constexpr int BB   = 128;
constexpr int CC   = 64;
constexpr int K1   = 192;    // 3*C perception channels
constexpr int M1   = 512;    // MLP dim
constexpr int HH   = 40;
constexpr int WW   = 40;
constexpr int PX   = 1600;   // H*W
constexpr int PXP  = 1664;   // padded to 26*64
constexpr float LN_EPS = 1e-5f;

constexpr int KP   = 384;    // perc row: [hi(192) | lo(192)] bf16
constexpr int W2K  = 1024;   // w2split row: [hi(512) | lo(512)] bf16

// ---------------------------------------------------------------------------
// Device scratch
// ---------------------------------------------------------------------------
__device__ __nv_bfloat16 g_perc[(size_t)BB * PXP * KP];   // 163 MB
__device__ float         g_y[(size_t)BB * PXP * M1];      // 436 MB (compacted rows)
__device__ __nv_bfloat16 g_w1s[M1 * KP];                  // [512][384]
__device__ __nv_bfloat16 g_w2s[CC * W2K];                 // [64][1024]
__device__ float         g_lnwT[(size_t)PX * M1];         // [p][m]
__device__ float         g_lnbT[(size_t)PX * M1];
__device__ float         g_part[BB * 52 * 2];
__device__ float         g_stats[BB * 2];
__device__ int           g_plist[PX];                     // compacted px list
__device__ int           g_cidx[PX];                      // px -> compact idx or -1
__device__ int           g_cnt;

// ---------------------------------------------------------------------------
// Helpers (base-ISA only: ldmatrix / mma.sync / cp.async)
// ---------------------------------------------------------------------------
__device__ __forceinline__ uint32_t smem_u32(const void* p) {
    uint32_t a;
    asm("{ .reg .u64 t; cvta.to.shared.u64 t, %1; cvt.u32.u64 %0, t; }"
        : "=r"(a) : "l"(p));
    return a;
}
#define SW128(o) ((o) ^ (((o) >> 3) & 0x70))

__device__ __forceinline__ void sts128(uint32_t a, uint4 v) {
    asm volatile("st.shared.v4.b32 [%0], {%1,%2,%3,%4};"
                 :: "r"(a), "r"(v.x), "r"(v.y), "r"(v.z), "r"(v.w) : "memory");
}
__device__ __forceinline__ void cp16(uint32_t dst, const void* src) {
    asm volatile("cp.async.cg.shared.global [%0], [%1], 16;"
                 :: "r"(dst), "l"(src) : "memory");
}
#define CP_COMMIT() asm volatile("cp.async.commit_group;" ::: "memory")
#define CP_WAIT(n)  asm volatile("cp.async.wait_group %0;" :: "n"(n) : "memory")

__device__ __forceinline__ void ldm_x4(uint32_t addr, uint32_t& r0, uint32_t& r1,
                                       uint32_t& r2, uint32_t& r3) {
    asm volatile("ldmatrix.sync.aligned.m8n8.x4.shared.b16 {%0,%1,%2,%3}, [%4];"
                 : "=r"(r0), "=r"(r1), "=r"(r2), "=r"(r3) : "r"(addr));
}
__device__ __forceinline__ void mma_bf16(float* c, const uint32_t* a,
                                         uint32_t b0, uint32_t b1) {
    asm volatile(
        "mma.sync.aligned.m16n8k16.row.col.f32.bf16.bf16.f32 "
        "{%0,%1,%2,%3},{%4,%5,%6,%7},{%8,%9},{%0,%1,%2,%3};"
        : "+f"(c[0]), "+f"(c[1]), "+f"(c[2]), "+f"(c[3])
        : "r"(a[0]), "r"(a[1]), "r"(a[2]), "r"(a[3]), "r"(b0), "r"(b1));
}

__device__ __forceinline__ void split_bf16(float v, __nv_bfloat16& h, __nv_bfloat16& l) {
    h = __float2bfloat16_rn(v);
    l = __float2bfloat16_rn(v - __bfloat162float(h));
}
__device__ __forceinline__ uint32_t pack2(__nv_bfloat16 a, __nv_bfloat16 b) {
    return (uint32_t)__bfloat16_as_ushort(a) | ((uint32_t)__bfloat16_as_ushort(b) << 16);
}

// ---------------------------------------------------------------------------
// Kernel 0a: weight splits + ln transpose
// ---------------------------------------------------------------------------
constexpr int PREPW_TOTAL = M1 * K1 + CC * M1 + 2 * M1 * PX;

__global__ void prepw_kernel(const float* __restrict__ w1, const float* __restrict__ w2,
                             const float* __restrict__ lnw, const float* __restrict__ lnb) {
    int idx = blockIdx.x * blockDim.x + threadIdx.x;
    if (idx >= PREPW_TOTAL) return;
    if (idx < M1 * K1) {
        int m = idx / K1, k = idx % K1;
        __nv_bfloat16 h, l; split_bf16(w1[idx], h, l);
        g_w1s[m * KP + k] = h;
        g_w1s[m * KP + K1 + k] = l;
    } else if (idx < M1 * K1 + CC * M1) {
        int j = idx - M1 * K1;
        int m = j / M1, k = j % M1;
        __nv_bfloat16 h, l; split_bf16(w2[j], h, l);
        g_w2s[m * W2K + k] = h;
        g_w2s[m * W2K + M1 + k] = l;
    } else if (idx < M1 * K1 + CC * M1 + M1 * PX) {
        int j = idx - M1 * K1 - CC * M1;
        int p = j / M1, m = j % M1;
        g_lnwT[(size_t)p * M1 + m] = lnw[(size_t)m * PX + p];
    } else {
        int j = idx - M1 * K1 - CC * M1 - M1 * PX;
        int p = j / M1, m = j % M1;
        g_lnbT[(size_t)p * M1 + m] = lnb[(size_t)m * PX + p];
    }
}

// ---------------------------------------------------------------------------
// Kernel 0b: mask compaction (deterministic order)
// ---------------------------------------------------------------------------
__global__ void compact_kernel(const int* __restrict__ mask) {
    __shared__ int sm[PX];
    int tid = threadIdx.x;
    for (int i = tid; i < PX; i += 256) sm[i] = mask[i];
    __syncthreads();
    if (tid == 0) {
        int c = 0;
        for (int p = 0; p < PX; p++) {
            if (sm[p] != 0) { g_plist[c] = p; g_cidx[p] = c; c++; }
            else            { g_cidx[p] = -1; }
        }
        g_cnt = c;
    }
}

// ---------------------------------------------------------------------------
// Kernel 0c: out = state (masked-off pixels keep state unchanged)
// ---------------------------------------------------------------------------
__global__ void outinit_kernel(const float* __restrict__ state, float* __restrict__ out) {
    size_t i = (size_t)blockIdx.x * blockDim.x + threadIdx.x;
    const float4* s = reinterpret_cast<const float4*>(state);
    float4* o = reinterpret_cast<float4*>(out);
    size_t n4 = (size_t)BB * CC * PX / 4;
    if (i < n4) o[i] = s[i];
}

// ---------------------------------------------------------------------------
// Kernel 0d: zero pad rows of g_perc (px 1600..1663)
// ---------------------------------------------------------------------------
__global__ void percpad_kernel() {
    int b = blockIdx.x;
    int tid = threadIdx.x;
    uint4 z = make_uint4(0, 0, 0, 0);
    uint4* dst = reinterpret_cast<uint4*>(g_perc + ((size_t)b * PXP + PX) * KP);
    // 64 rows * 384 bf16 = 49152 B = 3072 uint4
#pragma unroll
    for (int i = 0; i < 12; i++) dst[tid + i * 256] = z;
}

// ---------------------------------------------------------------------------
// Kernel 1: perception. One block per (b, image row h). 320 threads:
//   thread = (c, seg): c=tid/5, 8-px segment seg=tid%5.
//   Row-register reuse: 3 rows x (2 LDG.128 + 2 scalar) per thread -> 24 outputs.
//   Stage [40][384] bf16 in smem, coalesced store to g_perc.
// ---------------------------------------------------------------------------
__global__ __launch_bounds__(320) void perc_kernel(const float* __restrict__ state) {
    __shared__ __nv_bfloat16 sp[HH][KP];   // 30720 B
    int h = blockIdx.x;
    int b = blockIdx.y;
    int tid = threadIdx.x;
    int c   = tid / 5;
    int seg = tid % 5;
    int w0  = seg * 8;

    const float* s = state + ((size_t)b * CC + c) * PX;
    float v[3][10];
#pragma unroll
    for (int r = 0; r < 3; r++) {
        int hh = h + r - 1;
        if (hh >= 0 && hh < HH) {
            const float* rp = s + hh * WW;
            float4 a = *reinterpret_cast<const float4*>(rp + w0);
            float4 d = *reinterpret_cast<const float4*>(rp + w0 + 4);
            v[r][0] = (w0 > 0) ? rp[w0 - 1] : 0.f;
            v[r][1] = a.x; v[r][2] = a.y; v[r][3] = a.z; v[r][4] = a.w;
            v[r][5] = d.x; v[r][6] = d.y; v[r][7] = d.z; v[r][8] = d.w;
            v[r][9] = (w0 + 8 < WW) ? rp[w0 + 8] : 0.f;
        } else {
#pragma unroll
            for (int q = 0; q < 10; q++) v[r][q] = 0.f;
        }
    }
#pragma unroll
    for (int i = 0; i < 8; i++) {
        float sx = -v[0][i] + v[0][i + 2] - 2.f * v[1][i] + 2.f * v[1][i + 2]
                   - v[2][i] + v[2][i + 2];
        float sy = -v[0][i] - 2.f * v[0][i + 1] - v[0][i + 2]
                   + v[2][i] + 2.f * v[2][i + 1] + v[2][i + 2];
        float id = v[1][i + 1];
        __nv_bfloat16 h0, l0, h1, l1, h2, l2;
        split_bf16(sx, h0, l0);
        split_bf16(sy, h1, l1);
        split_bf16(id, h2, l2);
        int w = w0 + i;
        sp[w][3 * c + 0] = h0;  sp[w][K1 + 3 * c + 0] = l0;
        sp[w][3 * c + 1] = h1;  sp[w][K1 + 3 * c + 1] = l1;
        sp[w][3 * c + 2] = h2;  sp[w][K1 + 3 * c + 2] = l2;
    }
    __syncthreads();
    // coalesced store: 40*384 bf16 = 1920 uint4, 320 threads x 6
    const uint4* src = reinterpret_cast<const uint4*>(&sp[0][0]);
    uint4* dst = reinterpret_cast<uint4*>(g_perc + ((size_t)b * PXP + h * WW) * KP);
#pragma unroll
    for (int i = 0; i < 6; i++) dst[tid + i * 320] = src[tid + i * 320];
}

// ---------------------------------------------------------------------------
// Kernel 2: GEMM1 (mma.sync bf16) tiles 64px x 256mlp, K'=576 (9x64 chunks).
//   256 threads, 80KB smem (2 CTAs/SM). Stats over all px; y stored only for
//   masked px (compact row index).
// ---------------------------------------------------------------------------
__constant__ int AOFF1[9] = {0, 64, 128, 0, 64, 128, 192, 256, 320};
__constant__ int BOFF1[9] = {0, 64, 128, 192, 256, 320, 0, 64, 128};

__global__ __launch_bounds__(256) void gemm1_kernel() {
    extern __shared__ char dsm[];   // per stage: A 8KB | B 32KB; 2 stages = 80KB
    __shared__ float red[256];
    uint32_t base = smem_u32(dsm);
    int tid = threadIdx.x;
    int lane = tid & 31, wid = tid >> 5;
    int nt = blockIdx.x;   // 0..1  (mlp half)
    int pt = blockIdx.y;   // 0..25 (px tile of 64)
    int b  = blockIdx.z;

    const __nv_bfloat16* Ab = g_perc + ((size_t)b * PXP + pt * 64) * KP;
    const __nv_bfloat16* Bb = g_w1s + (size_t)(nt * 256) * KP;

    int m0 = (wid & 1) * 32;
    int n0 = (wid >> 1) * 64;
    int a_row  = m0 + (lane & 15);
    int a_byte = (lane >> 4) << 4;
    int qq     = lane >> 3;
    int b_row  = n0 + ((qq >> 1) << 3) + (lane & 7);
    int b_byte = (qq & 1) << 4;

    float acc[2][8][4] = {};

    // prologue: stage 0
    {
        uint32_t sA = base, sB = base + 8192;
#pragma unroll
        for (int i = 0; i < 2; i++) {
            int g = tid + i * 256, r = g >> 3, c = g & 7;
            cp16(sA + SW128(r * 128 + c * 16), Ab + (size_t)r * KP + 0 + c * 8);
        }
#pragma unroll
        for (int i = 0; i < 8; i++) {
            int g = tid + i * 256, r = g >> 3, c = g & 7;
            cp16(sB + SW128(r * 128 + c * 16), Bb + (size_t)r * KP + 0 + c * 8);
        }
        CP_COMMIT();
    }

    for (int ch = 0; ch < 9; ch++) {
        if (ch < 8) {
            int st = (ch + 1) & 1;
            int ao = AOFF1[ch + 1], bo = BOFF1[ch + 1];
            uint32_t sA = base + st * 40960, sB = sA + 8192;
#pragma unroll
            for (int i = 0; i < 2; i++) {
                int g = tid + i * 256, r = g >> 3, c = g & 7;
                cp16(sA + SW128(r * 128 + c * 16), Ab + (size_t)r * KP + ao + c * 8);
            }
#pragma unroll
            for (int i = 0; i < 8; i++) {
                int g = tid + i * 256, r = g >> 3, c = g & 7;
                cp16(sB + SW128(r * 128 + c * 16), Bb + (size_t)r * KP + bo + c * 8);
            }
            CP_COMMIT();
            CP_WAIT(1);
        } else {
            CP_WAIT(0);
        }
        __syncthreads();
        uint32_t sA = base + (ch & 1) * 40960;
        uint32_t sB = sA + 8192;
#pragma unroll
        for (int kk = 0; kk < 4; kk++) {
            int kb = kk * 32;
            uint32_t a[2][4];
#pragma unroll
            for (int mi = 0; mi < 2; mi++)
                ldm_x4(sA + SW128((a_row + mi * 16) * 128 + kb + a_byte),
                       a[mi][0], a[mi][1], a[mi][2], a[mi][3]);
            uint32_t bf[4][4];
#pragma unroll
            for (int n2 = 0; n2 < 4; n2++)
                ldm_x4(sB + SW128((b_row + n2 * 16) * 128 + kb + b_byte),
                       bf[n2][0], bf[n2][1], bf[n2][2], bf[n2][3]);
#pragma unroll
            for (int mi = 0; mi < 2; mi++)
#pragma unroll
                for (int ni = 0; ni < 8; ni++)
                    mma_bf16(acc[mi][ni], a[mi],
                             bf[ni >> 1][(ni & 1) * 2], bf[ni >> 1][(ni & 1) * 2 + 1]);
        }
        __syncthreads();
    }

    // epilogue: stats over all, y stored only for masked px (compacted row)
    float s = 0.f, s2 = 0.f;
#pragma unroll
    for (int mi = 0; mi < 2; mi++)
#pragma unroll
        for (int ni = 0; ni < 8; ni++) {
            float* c = acc[mi][ni];
            s  += c[0] + c[1] + c[2] + c[3];
            s2 += c[0] * c[0] + c[1] * c[1] + c[2] * c[2] + c[3] * c[3];
        }
#pragma unroll
    for (int mi = 0; mi < 2; mi++)
#pragma unroll
        for (int half = 0; half < 2; half++) {
            int r  = m0 + mi * 16 + (lane >> 2) + half * 8;
            int px = pt * 64 + r;
            int ci = (px < PX) ? g_cidx[px] : -1;
            if (ci >= 0) {
                float* rowp = g_y + ((size_t)b * PXP + ci) * M1
                              + nt * 256 + n0 + (lane & 3) * 2;
#pragma unroll
                for (int ni = 0; ni < 8; ni++)
                    *reinterpret_cast<float2*>(rowp + ni * 8) =
                        make_float2(acc[mi][ni][half * 2], acc[mi][ni][half * 2 + 1]);
            }
        }

    red[tid] = s;
    __syncthreads();
    for (int o = 128; o > 0; o >>= 1) {
        if (tid < o) red[tid] += red[tid + o];
        __syncthreads();
    }
    float bs = red[0];
    __syncthreads();
    red[tid] = s2;
    __syncthreads();
    for (int o = 128; o > 0; o >>= 1) {
        if (tid < o) red[tid] += red[tid + o];
        __syncthreads();
    }
    if (tid == 0) {
        int pi = (b * 26 + pt) * 2 + nt;
        g_part[pi * 2 + 0] = bs;
        g_part[pi * 2 + 1] = red[0];
    }
}

// ---------------------------------------------------------------------------
// Kernel 3: per-sample LN stats (deterministic fixed order)
// ---------------------------------------------------------------------------
__global__ void stats_kernel() {
    int b = threadIdx.x;
    if (b >= BB) return;
    float s = 0.f, s2 = 0.f;
    for (int i = 0; i < 52; i++) {
        s  += g_part[(b * 52 + i) * 2 + 0];
        s2 += g_part[(b * 52 + i) * 2 + 1];
    }
    float inv = 1.f / (float)(M1 * PX);
    float mu  = s * inv;
    float var = s2 * inv - mu * mu;
    g_stats[b * 2 + 0] = mu;
    g_stats[b * 2 + 1] = rsqrtf(var + LN_EPS);
}

// ---------------------------------------------------------------------------
// Kernel 4: GEMM2 over COMPACTED pixels. Z[128cp,64c] = relu(LN(Y)) @ w2^T
//   (3-product split, merged k-loop). Fused alive/residual scatter epilogue.
// ---------------------------------------------------------------------------
__global__ __launch_bounds__(256) void gemm2_kernel(
    const float* __restrict__ state, float* __restrict__ out) {
    extern __shared__ char dsm[];   // Ah 16K | Al 16K | Bh 8K | Bl 8K = 48KB
    __shared__ float scl[128];
    __shared__ int   spx[128];
    uint32_t sAh = smem_u32(dsm);
    uint32_t sAl = sAh + 16384;
    uint32_t sBh = sAh + 32768;
    uint32_t sBl = sAh + 40960;

    int cnt = g_cnt;
    int ct = blockIdx.x;
    if (ct * 128 >= cnt) return;
    int b  = blockIdx.y;

    int tid = threadIdx.x, lane = tid & 31, wid = tid >> 5;
    float mu   = g_stats[b * 2 + 0];
    float rstd = g_stats[b * 2 + 1];

    if (tid < 128) {
        int cp = ct * 128 + tid;
        float sc = 0.f;
        int px = 0;
        if (cp < cnt) {
            px = g_plist[cp];
            int h = px / WW, w = px % WW;
            const float* alive = state + ((size_t)b * CC + 3) * PX;
            float mx = -1e30f;
#pragma unroll
            for (int dy = -1; dy <= 1; dy++)
#pragma unroll
                for (int dx = -1; dx <= 1; dx++) {
                    int hh = h + dy, ww2 = w + dx;
                    if (hh >= 0 && hh < HH && ww2 >= 0 && ww2 < WW)
                        mx = fmaxf(mx, alive[hh * WW + ww2]);
                }
            sc = (mx > 0.1f) ? 1.f : 0.f;   // mask==1 guaranteed on compacted px
        }
        scl[tid] = sc;
        spx[tid] = px;
    }

    int m0 = (wid & 3) * 32;
    int n0 = (wid >> 2) * 32;
    int a_row  = m0 + (lane & 15);
    int a_byte = (lane >> 4) << 4;
    int qq     = lane >> 3;
    int b_row  = n0 + ((qq >> 1) << 3) + (lane & 7);
    int b_byte = (qq & 1) << 4;

    float acc[2][4][4] = {};

    for (int ch = 0; ch < 8; ch++) {
        int c0 = ch * 64;
        __syncthreads();   // prev mma done before overwriting tiles
#pragma unroll
        for (int i = 0; i < 2; i++) {
            int g = tid + i * 256, r = g >> 3, c = g & 7;
            cp16(sBh + SW128(r * 128 + c * 16), g_w2s + (size_t)r * W2K + c0 + c * 8);
            cp16(sBl + SW128(r * 128 + c * 16), g_w2s + (size_t)r * W2K + M1 + c0 + c * 8);
        }
        CP_COMMIT();
        // A tiles: gathered y -> LN -> ReLU -> split -> Ah/Al
#pragma unroll
        for (int i = 0; i < 4; i++) {
            int g = tid + i * 256, r = g >> 3, c = g & 7;
            int cp = ct * 128 + r;
            float z[8];
            if (cp < cnt) {
                int px = spx[r];
                const float* yp = g_y   + ((size_t)b * PXP + cp) * M1 + c0 + c * 8;
                const float* wp = g_lnwT + (size_t)px * M1 + c0 + c * 8;
                const float* bp = g_lnbT + (size_t)px * M1 + c0 + c * 8;
#pragma unroll
                for (int q2 = 0; q2 < 2; q2++) {
                    float4 y = *reinterpret_cast<const float4*>(yp + q2 * 4);
                    float4 w = *reinterpret_cast<const float4*>(wp + q2 * 4);
                    float4 bb = *reinterpret_cast<const float4*>(bp + q2 * 4);
                    z[q2 * 4 + 0] = fmaxf((y.x - mu) * rstd * w.x + bb.x, 0.f);
                    z[q2 * 4 + 1] = fmaxf((y.y - mu) * rstd * w.y + bb.y, 0.f);
                    z[q2 * 4 + 2] = fmaxf((y.z - mu) * rstd * w.z + bb.z, 0.f);
                    z[q2 * 4 + 3] = fmaxf((y.w - mu) * rstd * w.w + bb.w, 0.f);
                }
            } else {
#pragma unroll
                for (int q2 = 0; q2 < 8; q2++) z[q2] = 0.f;
            }
            __nv_bfloat16 h[8], l[8];
#pragma unroll
            for (int q2 = 0; q2 < 8; q2++) split_bf16(z[q2], h[q2], l[q2]);
            sts128(sAh + SW128(r * 128 + c * 16),
                   make_uint4(pack2(h[0], h[1]), pack2(h[2], h[3]),
                              pack2(h[4], h[5]), pack2(h[6], h[7])));
            sts128(sAl + SW128(r * 128 + c * 16),
                   make_uint4(pack2(l[0], l[1]), pack2(l[2], l[3]),
                              pack2(l[4], l[5]), pack2(l[6], l[7])));
        }
        CP_WAIT(0);
        __syncthreads();
        // merged k-loop: frags loaded once, 3 split products
#pragma unroll
        for (int kk = 0; kk < 4; kk++) {
            int kb = kk * 32;
            uint32_t ah[2][4], al[2][4];
#pragma unroll
            for (int mi = 0; mi < 2; mi++) {
                ldm_x4(sAh + SW128((a_row + mi * 16) * 128 + kb + a_byte),
                       ah[mi][0], ah[mi][1], ah[mi][2], ah[mi][3]);
                ldm_x4(sAl + SW128((a_row + mi * 16) * 128 + kb + a_byte),
                       al[mi][0], al[mi][1], al[mi][2], al[mi][3]);
            }
            uint32_t bh[2][4], bl[2][4];
#pragma unroll
            for (int n2 = 0; n2 < 2; n2++) {
                ldm_x4(sBh + SW128((b_row + n2 * 16) * 128 + kb + b_byte),
                       bh[n2][0], bh[n2][1], bh[n2][2], bh[n2][3]);
                ldm_x4(sBl + SW128((b_row + n2 * 16) * 128 + kb + b_byte),
                       bl[n2][0], bl[n2][1], bl[n2][2], bl[n2][3]);
            }
#pragma unroll
            for (int mi = 0; mi < 2; mi++)
#pragma unroll
                for (int ni = 0; ni < 4; ni++) {
                    int n2 = ni >> 1, rr = (ni & 1) * 2;
                    mma_bf16(acc[mi][ni], ah[mi], bh[n2][rr], bh[n2][rr + 1]);
                    mma_bf16(acc[mi][ni], ah[mi], bl[n2][rr], bl[n2][rr + 1]);
                    mma_bf16(acc[mi][ni], al[mi], bh[n2][rr], bh[n2][rr + 1]);
                }
        }
    }

    // epilogue: scatter out[b][c][px] = state + z * scl for compacted px
#pragma unroll
    for (int mi = 0; mi < 2; mi++)
#pragma unroll
        for (int ni = 0; ni < 4; ni++) {
            int rl0 = m0 + mi * 16 + (lane >> 2);
            int cc  = n0 + ni * 8 + (lane & 3) * 2;
#pragma unroll
            for (int hf = 0; hf < 2; hf++) {
                int rl = rl0 + hf * 8;
                int cp = ct * 128 + rl;
                if (cp < cnt) {
                    int px = spx[rl];
                    float sc = scl[rl];
                    size_t o0 = ((size_t)b * CC + cc) * PX + px;
                    out[o0]      = state[o0]      + acc[mi][ni][hf * 2 + 0] * sc;
                    out[o0 + PX] = state[o0 + PX] + acc[mi][ni][hf * 2 + 1] * sc;
                }
            }
        }
}

// ---------------------------------------------------------------------------
extern "C" void kernel_launch(void* const* d_in, const int* in_sizes, int n_in,
                              void* d_out, int out_size) {
    const float* state = (const float*)d_in[0];
    const float* w1    = (const float*)d_in[1];
    const float* lnw   = (const float*)d_in[2];
    const float* lnb   = (const float*)d_in[3];
    const float* w2    = (const float*)d_in[4];
    const int*   mask  = (const int*)d_in[5];
    float* out = (float*)d_out;

    cudaFuncSetAttribute(gemm1_kernel, cudaFuncAttributeMaxDynamicSharedMemorySize, 81920);
    cudaFuncSetAttribute(gemm2_kernel, cudaFuncAttributeMaxDynamicSharedMemorySize, 49152);

    prepw_kernel<<<(PREPW_TOTAL + 255) / 256, 256>>>(w1, w2, lnw, lnb);
    compact_kernel<<<1, 256>>>(mask);
    outinit_kernel<<<(BB * CC * PX / 4 + 255) / 256, 256>>>(state, out);
    percpad_kernel<<<BB, 256>>>();
    perc_kernel<<<dim3(HH, BB), 320>>>(state);
    gemm1_kernel<<<dim3(2, 26, BB), 256, 81920>>>();
    stats_kernel<<<1, 128>>>();
    gemm2_kernel<<<dim3(13, BB), 256, 49152>>>(state, out);
}